// round 7
// baseline (speedup 1.0000x reference)
#include <cuda_runtime.h>
#include <cuda_fp16.h>
#include <math.h>
#include <stdint.h>

// Problem: inputs (64,64,64,64) fp32, codebook (1024,64) fp32
#define N_ROWS   262144
#define DIM      64
#define KCODES   1024
#define ND_ELEMS (N_ROWS * DIM)

#define THREADS  512              // 16 warps, each owns m16 rows
#define M_CTA    256
#define CTAS     (N_ROWS / M_CTA) // 1024
#define CHUNK_N  128
#define NCHUNKS  (KCODES / CHUNK_N)

// smem layout (bytes)
#define SMB_ALO    0               // A_lo: 256 rows x 128B (fp16)      32768
#define SMB_B      32768           // B [buf][hi/lo] 16KB planes        65536
#define SMB_CN     98304           // cnorm                              4096
#define SMB_RED    102400          // reduction scratch                    64
#define SMEM_BYTES 102464

// ---------------------------------------------------------------------------
__device__ float        g_cnorm[KCODES];
__device__ unsigned int g_counts[KCODES];
__device__ double       g_sse;
__device__ __align__(16) __half g_cbh[KCODES * DIM];   // fp16 hi
__device__ __align__(16) __half g_cbl[KCODES * DIM];   // fp16 lo

// ---------------------------------------------------------------------------
__device__ __forceinline__ uint32_t smem_u32(const void* p) {
    uint32_t a;
    asm("{ .reg .u64 t; cvta.to.shared.u64 t, %1; cvt.u32.u64 %0, t; }" : "=r"(a) : "l"(p));
    return a;
}
__device__ __forceinline__ void cp_async16(uint32_t dst, const void* src) {
    asm volatile("cp.async.cg.shared.global [%0], [%1], 16;" :: "r"(dst), "l"(src));
}
#define CP_COMMIT() asm volatile("cp.async.commit_group;" ::: "memory")

#define LDM4(r0, r1, r2, r3, addr) \
    asm volatile("ldmatrix.sync.aligned.m8n8.x4.shared.b16 {%0,%1,%2,%3}, [%4];" \
        : "=r"(r0), "=r"(r1), "=r"(r2), "=r"(r3) : "r"(addr))

#define STS128(addr, p0, p1, p2, p3) \
    asm volatile("st.shared.v4.b32 [%0], {%1,%2,%3,%4};" \
        :: "r"(addr), "r"(p0), "r"(p1), "r"(p2), "r"(p3) : "memory")

__device__ __forceinline__ void mma_f16(float d[4], uint32_t a0, uint32_t a1,
                                        uint32_t a2, uint32_t a3,
                                        uint32_t b0, uint32_t b1) {
    asm volatile(
        "mma.sync.aligned.m16n8k16.row.col.f32.f16.f16.f32 "
        "{%0,%1,%2,%3},{%4,%5,%6,%7},{%8,%9},{%0,%1,%2,%3};"
        : "+f"(d[0]), "+f"(d[1]), "+f"(d[2]), "+f"(d[3])
        : "r"(a0), "r"(a1), "r"(a2), "r"(a3), "r"(b0), "r"(b1));
}

// fp16 hi/lo split of a float2, packed as half2 words
__device__ __forceinline__ void split2(float2 v, uint32_t& h, uint32_t& l) {
    __half hx = __float2half_rn(v.x), hy = __float2half_rn(v.y);
    float lx = v.x - __half2float(hx), ly = v.y - __half2float(hy);
    __half2 hh = __halves2half2(hx, hy);
    __half2 ll = __floats2half2_rn(lx, ly);
    h = *reinterpret_cast<uint32_t*>(&hh);
    l = *reinterpret_cast<uint32_t*>(&ll);
}

// (a,ia) < (b,ib) with index tie-break
__device__ __forceinline__ bool dless(float a, int ia, float b, int ib) {
    return a < b || (a == b && ia < ib);
}
__device__ __forceinline__ void upd2(float& b1, int& i1, float& b2, int& i2,
                                     float d, int i) {
    if (d < b1)      { b2 = b1; i2 = i1; b1 = d; i1 = i; }
    else if (d < b2) { b2 = d;  i2 = i; }
}
__device__ __forceinline__ void merge2(float& b1, int& i1, float& b2, int& i2,
                                       float c1, int ci1, float c2, int ci2) {
    if (dless(c1, ci1, b1, i1)) {
        if (dless(b1, i1, c2, ci2)) { b2 = b1; i2 = i1; }
        else                        { b2 = c2; i2 = ci2; }
        b1 = c1; i1 = ci1;
    } else if (dless(c1, ci1, b2, i2)) {
        b2 = c1; i2 = ci1;
    }
}

// ---------------------------------------------------------------------------
// Kernel 1: fp16 hi/lo split of codebook + cnorm + zero accumulators
// ---------------------------------------------------------------------------
__global__ void vq_split(const float* __restrict__ codebook) {
    __shared__ float s_part[32];
    const int base = blockIdx.x * 1024;
    const int idx  = base + threadIdx.x;
    float x  = codebook[idx];
    __half h = __float2half_rn(x);
    g_cbh[idx] = h;
    g_cbl[idx] = __float2half_rn(x - __half2float(h));

    float p = x * x;
    #pragma unroll
    for (int o = 16; o > 0; o >>= 1) p += __shfl_down_sync(0xffffffffu, p, o);
    const int w = threadIdx.x >> 5;
    if ((threadIdx.x & 31) == 0) s_part[w] = p;
    __syncthreads();
    if (threadIdx.x < 16) {
        g_cnorm[base / 64 + threadIdx.x] = s_part[2 * threadIdx.x] + s_part[2 * threadIdx.x + 1];
        g_counts[blockIdx.x * 16 + threadIdx.x] = 0u;
    }
    if (idx == 0) g_sse = 0.0;
}

// ---------------------------------------------------------------------------
// Kernel 2: fp16 3-way-split tensor distances + best-2 argmin + fp32 refine
//           A_hi in registers, A_lo in smem (ldmatrix) -> 2 CTAs/SM
// ---------------------------------------------------------------------------
__global__ __launch_bounds__(THREADS, 2)
void vq_tc(const float* __restrict__ inputs,
           const float* __restrict__ codebook,
           float* __restrict__ out_q,
           float* __restrict__ out_tok) {
    extern __shared__ float smf[];
    const uint32_t smb = smem_u32(smf);
    float* s_cn = (float*)((char*)smf + SMB_CN);
    float* s_rd = (float*)((char*)smf + SMB_RED);

    const int tid  = threadIdx.x;
    const int w    = tid >> 5;
    const int lane = tid & 31;
    const int grp  = lane >> 2;        // m-row within tile (0..7)
    const int qt   = lane & 3;         // k-thread in quad

    const int blk_row = blockIdx.x * M_CTA;
    const int r0 = blk_row + w * 16 + grp;
    const int r1 = r0 + 8;

    // ---- B chunk loader: 4 x cp.async(16B) per thread ----
    const int lv  = tid >> 8;          // 0 = hi, 1 = lo
    const int rr  = tid & 255;
    const int lnl = rr >> 1;           // code within chunk
    const int lu0 = (rr & 1) * 4;      // first k-unit
    #define LOAD_CHUNK(c, buf) do {                                                  \
        const __half* _src = (lv ? g_cbl : g_cbh)                                    \
                           + ((size_t)((c) * CHUNK_N + lnl)) * DIM;                  \
        uint32_t _dst = smb + SMB_B                                                  \
                      + (uint32_t)((buf) * 32768 + lv * 16384 + lnl * 128);          \
        _Pragma("unroll")                                                            \
        for (int _j = 0; _j < 4; _j++) {                                             \
            int _u = lu0 + _j;                                                       \
            cp_async16(_dst + ((_u ^ (lnl & 7)) * 16), _src + _u * 8);               \
        }                                                                            \
        CP_COMMIT();                                                                 \
    } while (0)

    LOAD_CHUNK(0, 0);

    // ---- stage A_lo to smem: thread covers row tid>>1, 4 k-units ----
    {
        const int arow = tid >> 1;
        const int u0   = (tid & 1) * 4;
        const float* xin = inputs + (size_t)(blk_row + arow) * DIM + u0 * 8;
        const uint32_t abase = smb + SMB_ALO + (uint32_t)(arow * 128);
        #pragma unroll
        for (int j = 0; j < 4; j++) {
            float4 va = *(const float4*)(xin + j * 8);
            float4 vb = *(const float4*)(xin + j * 8 + 4);
            uint32_t l0, l1, l2, l3, hdum;
            split2(make_float2(va.x, va.y), hdum, l0);
            split2(make_float2(va.z, va.w), hdum, l1);
            split2(make_float2(vb.x, vb.y), hdum, l2);
            split2(make_float2(vb.z, vb.w), hdum, l3);
            STS128(abase + (uint32_t)((((u0 + j) ^ (arow & 7)) * 16)), l0, l1, l2, l3);
        }
    }

    // ---- A_hi fragments in registers ----
    uint32_t ahi[4][4];
    {
        const float* x0 = inputs + (size_t)r0 * DIM;
        const float* x1 = inputs + (size_t)r1 * DIM;
        uint32_t dum;
        #pragma unroll
        for (int s = 0; s < 4; s++) {
            const int k0 = 16 * s + 2 * qt;
            split2(*(const float2*)(x0 + k0),     ahi[s][0], dum);
            split2(*(const float2*)(x1 + k0),     ahi[s][1], dum);
            split2(*(const float2*)(x0 + k0 + 8), ahi[s][2], dum);
            split2(*(const float2*)(x1 + k0 + 8), ahi[s][3], dum);
        }
    }

    // ---- cnorm to smem ----
    #pragma unroll
    for (int i = tid; i < KCODES; i += THREADS) s_cn[i] = g_cnorm[i];

    // ldmatrix per-lane address components
    const int nloc = ((lane >> 4) & 1) * 8 + (lane & 7);  // B row within pair
    const int ubit = (lane >> 3) & 1;                     // B k-unit parity
    const int s7   = lane & 7;                            // swizzle key
    // A_lo ldmatrix: row = w*16 + (lane & 15), unit = (2s | (lane>>4)) ^ (lane&7)
    const uint32_t aldbase = smb + SMB_ALO + (uint32_t)((w * 16 + (lane & 15)) * 128);
    const int     albit    = (lane >> 4) & 1;

    float b1[2] = { 3.402823466e38f, 3.402823466e38f };
    float b2[2] = { 3.402823466e38f, 3.402823466e38f };
    int   i1[2] = { 0, 0 }, i2[2] = { 0, 0 };

    for (int c = 0; c < NCHUNKS; c++) {
        if (c + 1 < NCHUNKS) {
            LOAD_CHUNK(c + 1, (c + 1) & 1);
            asm volatile("cp.async.wait_group 1;" ::: "memory");
        } else {
            asm volatile("cp.async.wait_group 0;" ::: "memory");
        }
        __syncthreads();

        const uint32_t rowH = smb + SMB_B + (uint32_t)((c & 1) * 32768) + nloc * 128;

        #pragma unroll
        for (int p = 0; p < 8; p++) {           // pair of n-frags = 16 codes
            float acc0[4] = {0.f, 0.f, 0.f, 0.f};
            float acc1[4] = {0.f, 0.f, 0.f, 0.f};
            const uint32_t rbase = rowH + p * 2048;

            #pragma unroll
            for (int s = 0; s < 4; s++) {       // k16 steps
                const uint32_t uoff = (uint32_t)(((2 * s + ubit) ^ s7) * 16);
                const uint32_t aoff = (uint32_t)((((2 * s) | albit) ^ s7) * 16);
                uint32_t bh0, bh1, bh2, bh3, bl0, bl1, bl2, bl3;
                uint32_t al0, al1, al2, al3;
                LDM4(bh0, bh1, bh2, bh3, rbase + uoff);            // hi B
                LDM4(bl0, bl1, bl2, bl3, rbase + 16384 + uoff);    // lo B
                LDM4(al0, al1, al2, al3, aldbase + aoff);          // lo A
                mma_f16(acc0, ahi[s][0], ahi[s][1], ahi[s][2], ahi[s][3], bh0, bh1);
                mma_f16(acc1, ahi[s][0], ahi[s][1], ahi[s][2], ahi[s][3], bh2, bh3);
                mma_f16(acc0, ahi[s][0], ahi[s][1], ahi[s][2], ahi[s][3], bl0, bl1);
                mma_f16(acc1, ahi[s][0], ahi[s][1], ahi[s][2], ahi[s][3], bl2, bl3);
                mma_f16(acc0, al0, al1, al2, al3, bh0, bh1);
                mma_f16(acc1, al0, al1, al2, al3, bh2, bh3);
            }

            // epilogue: dist = |c|^2 - 2*dot, best-2 (ascending index order)
            const int g0 = c * CHUNK_N + p * 16 + 2 * qt;
            const int g1 = g0 + 8;
            const float cn00 = s_cn[g0], cn01 = s_cn[g0 + 1];
            const float cn10 = s_cn[g1], cn11 = s_cn[g1 + 1];
            upd2(b1[0], i1[0], b2[0], i2[0], cn00 - 2.0f * acc0[0], g0);
            upd2(b1[0], i1[0], b2[0], i2[0], cn01 - 2.0f * acc0[1], g0 + 1);
            upd2(b1[1], i1[1], b2[1], i2[1], cn00 - 2.0f * acc0[2], g0);
            upd2(b1[1], i1[1], b2[1], i2[1], cn01 - 2.0f * acc0[3], g0 + 1);
            upd2(b1[0], i1[0], b2[0], i2[0], cn10 - 2.0f * acc1[0], g1);
            upd2(b1[0], i1[0], b2[0], i2[0], cn11 - 2.0f * acc1[1], g1 + 1);
            upd2(b1[1], i1[1], b2[1], i2[1], cn10 - 2.0f * acc1[2], g1);
            upd2(b1[1], i1[1], b2[1], i2[1], cn11 - 2.0f * acc1[3], g1 + 1);
        }
        __syncthreads();
    }

    // ---- per-row best-2 merge across the 4 k-lanes, then UNCONDITIONAL
    //      exact fp32 refine (all lanes execute every shuffle) ----
    float sse = 0.f;
    #pragma unroll
    for (int mt = 0; mt < 2; mt++) {
        float B1 = b1[mt], B2 = b2[mt];
        int   I1 = i1[mt], I2 = i2[mt];
        #pragma unroll
        for (int off = 1; off <= 2; off <<= 1) {
            float c1 = __shfl_xor_sync(0xffffffffu, B1, off);
            int  ci1 = __shfl_xor_sync(0xffffffffu, I1, off);
            float c2 = __shfl_xor_sync(0xffffffffu, B2, off);
            int  ci2 = __shfl_xor_sync(0xffffffffu, I2, off);
            merge2(B1, I1, B2, I2, c1, ci1, c2, ci2);
        }

        const int row = mt ? r1 : r0;

        const float* xr  = inputs + (size_t)row * DIM + qt * 16;
        const float* c1p = codebook + (size_t)I1 * DIM + qt * 16;
        const float* c2p = codebook + (size_t)I2 * DIM + qt * 16;
        float p1 = 0.f, p2 = 0.f;
        #pragma unroll
        for (int j = 0; j < 16; j++) {
            float xv = xr[j];
            p1 = fmaf(xv, c1p[j], p1);
            p2 = fmaf(xv, c2p[j], p2);
        }
        #pragma unroll
        for (int off = 1; off <= 2; off <<= 1) {
            p1 += __shfl_xor_sync(0xffffffffu, p1, off);
            p2 += __shfl_xor_sync(0xffffffffu, p2, off);
        }
        float e1 = s_cn[I1] - 2.0f * p1;
        float e2 = s_cn[I2] - 2.0f * p2;
        const int sel = dless(e2, I2, e1, I1) ? I2 : I1;

        const float4* cq  = (const float4*)(codebook + (size_t)sel * DIM) + qt * 4;
        const float4* xin = (const float4*)(inputs + (size_t)row * DIM) + qt * 4;
        float4* oq = (float4*)(out_q + (size_t)row * DIM) + qt * 4;
        #pragma unroll
        for (int g = 0; g < 4; g++) {
            float4 q = cq[g], x = xin[g];
            float dx = q.x - x.x, dy = q.y - x.y, dz = q.z - x.z, dw = q.w - x.w;
            sse += dx * dx + dy * dy + dz * dz + dw * dw;
            oq[g] = q;
        }
        if (qt == 0) {
            out_tok[row] = (float)sel;
            atomicAdd(&g_counts[sel], 1u);
        }
    }

    // ---- SSE block reduce ----
    #pragma unroll
    for (int o = 16; o > 0; o >>= 1) sse += __shfl_down_sync(0xffffffffu, sse, o);
    if (lane == 0) s_rd[w] = sse;
    __syncthreads();
    if (tid == 0) {
        float s = 0.f;
        #pragma unroll
        for (int i = 0; i < 16; i++) s += s_rd[i];
        atomicAdd(&g_sse, (double)s);
    }
}

// ---------------------------------------------------------------------------
// Kernel 3: perplexity + scalar losses
// ---------------------------------------------------------------------------
__global__ void vq_finalize(float* __restrict__ out_scalars) {
    __shared__ double s_red[32];
    const int j = threadIdx.x;
    double p    = (double)g_counts[j] / (double)N_ROWS;
    double term = p * log(p + 1e-10);
    #pragma unroll
    for (int o = 16; o > 0; o >>= 1)
        term += __shfl_down_sync(0xffffffffu, term, o);
    const int lane = j & 31, wid = j >> 5;
    if (lane == 0) s_red[wid] = term;
    __syncthreads();
    if (j == 0) {
        double tot = 0.0;
        #pragma unroll
        for (int w = 0; w < 32; w++) tot += s_red[w];
        double perp = exp(-tot);
        double L = g_sse / (double)ND_ELEMS;
        out_scalars[0] = (float)(1.25 * L);
        out_scalars[1] = (float)(0.25 * L);
        out_scalars[2] = (float)L;
        out_scalars[3] = (float)perp;
    }
}

// ---------------------------------------------------------------------------
extern "C" void kernel_launch(void* const* d_in, const int* in_sizes, int n_in,
                              void* d_out, int out_size) {
    const float* inputs   = (const float*)d_in[0];
    const float* codebook = (const float*)d_in[1];
    float* out = (float*)d_out;

    float* out_q       = out;
    float* out_tok     = out + ND_ELEMS;
    float* out_scalars = out + ND_ELEMS + N_ROWS;

    static int configured = 0;
    if (!configured) {
        cudaFuncSetAttribute(vq_tc, cudaFuncAttributeMaxDynamicSharedMemorySize, SMEM_BYTES);
        configured = 1;
    }

    vq_split<<<KCODES * DIM / 1024, 1024>>>(codebook);
    vq_tc<<<CTAS, THREADS, SMEM_BYTES>>>(inputs, codebook, out_q, out_tok);
    vq_finalize<<<1, 1024>>>(out_scalars);
}

// round 8
// speedup vs baseline: 1.1632x; 1.1632x over previous
#include <cuda_runtime.h>
#include <cuda_fp16.h>
#include <math.h>
#include <stdint.h>

// Problem: inputs (64,64,64,64) fp32, codebook (1024,64) fp32
#define N_ROWS   262144
#define DIM      64
#define KCODES   1024
#define ND_ELEMS (N_ROWS * DIM)

#define THREADS  512              // 16 warps, each owns m16 rows
#define M_CTA    256
#define CTAS     (N_ROWS / M_CTA) // 1024
#define CHUNK_N  128
#define NCHUNKS  (KCODES / CHUNK_N)

// smem bytes: B_hi [buf2][16KB] = 32KB, cnorm 4KB, red 64B
#define SMB_B      0
#define SMB_CN     32768
#define SMB_RED    36864
#define SMEM_BYTES 36928

// ---------------------------------------------------------------------------
__device__ float        g_cnorm[KCODES];
__device__ unsigned int g_counts[KCODES];
__device__ double       g_sse;
__device__ __align__(16) __half g_cbh[KCODES * DIM];   // fp16 hi of codebook

// ---------------------------------------------------------------------------
__device__ __forceinline__ uint32_t smem_u32(const void* p) {
    uint32_t a;
    asm("{ .reg .u64 t; cvta.to.shared.u64 t, %1; cvt.u32.u64 %0, t; }" : "=r"(a) : "l"(p));
    return a;
}
__device__ __forceinline__ void cp_async16(uint32_t dst, const void* src) {
    asm volatile("cp.async.cg.shared.global [%0], [%1], 16;" :: "r"(dst), "l"(src));
}
#define CP_COMMIT() asm volatile("cp.async.commit_group;" ::: "memory")

#define LDM4(r0, r1, r2, r3, addr) \
    asm volatile("ldmatrix.sync.aligned.m8n8.x4.shared.b16 {%0,%1,%2,%3}, [%4];" \
        : "=r"(r0), "=r"(r1), "=r"(r2), "=r"(r3) : "r"(addr))

__device__ __forceinline__ void mma_f16(float d[4], const uint32_t a[4],
                                        uint32_t b0, uint32_t b1) {
    asm volatile(
        "mma.sync.aligned.m16n8k16.row.col.f32.f16.f16.f32 "
        "{%0,%1,%2,%3},{%4,%5,%6,%7},{%8,%9},{%0,%1,%2,%3};"
        : "+f"(d[0]), "+f"(d[1]), "+f"(d[2]), "+f"(d[3])
        : "r"(a[0]), "r"(a[1]), "r"(a[2]), "r"(a[3]), "r"(b0), "r"(b1));
}

// fp16 hi/lo split of a float2, packed as half2 words
__device__ __forceinline__ void split2(float2 v, uint32_t& h, uint32_t& l) {
    __half hx = __float2half_rn(v.x), hy = __float2half_rn(v.y);
    float lx = v.x - __half2float(hx), ly = v.y - __half2float(hy);
    __half2 hh = __halves2half2(hx, hy);
    __half2 ll = __floats2half2_rn(lx, ly);
    h = *reinterpret_cast<uint32_t*>(&hh);
    l = *reinterpret_cast<uint32_t*>(&ll);
}

// (a,ia) < (b,ib) with index tie-break
__device__ __forceinline__ bool dless(float a, int ia, float b, int ib) {
    return a < b || (a == b && ia < ib);
}
__device__ __forceinline__ void upd2(float& b1, int& i1, float& b2, int& i2,
                                     float d, int i) {
    if (d < b1)      { b2 = b1; i2 = i1; b1 = d; i1 = i; }
    else if (d < b2) { b2 = d;  i2 = i; }
}
__device__ __forceinline__ void merge2(float& b1, int& i1, float& b2, int& i2,
                                       float c1, int ci1, float c2, int ci2) {
    if (dless(c1, ci1, b1, i1)) {
        if (dless(b1, i1, c2, ci2)) { b2 = b1; i2 = i1; }
        else                        { b2 = c2; i2 = ci2; }
        b1 = c1; i1 = ci1;
    } else if (dless(c1, ci1, b2, i2)) {
        b2 = c1; i2 = ci1;
    }
}

// ---------------------------------------------------------------------------
// Kernel 1: fp16 hi of codebook + cnorm + zero accumulators
// ---------------------------------------------------------------------------
__global__ void vq_split(const float* __restrict__ codebook) {
    __shared__ float s_part[32];
    const int base = blockIdx.x * 1024;
    const int idx  = base + threadIdx.x;
    float x  = codebook[idx];
    g_cbh[idx] = __float2half_rn(x);

    float p = x * x;
    #pragma unroll
    for (int o = 16; o > 0; o >>= 1) p += __shfl_down_sync(0xffffffffu, p, o);
    const int w = threadIdx.x >> 5;
    if ((threadIdx.x & 31) == 0) s_part[w] = p;
    __syncthreads();
    if (threadIdx.x < 16) {
        g_cnorm[base / 64 + threadIdx.x] = s_part[2 * threadIdx.x] + s_part[2 * threadIdx.x + 1];
        g_counts[blockIdx.x * 16 + threadIdx.x] = 0u;
    }
    if (idx == 0) g_sse = 0.0;
}

// ---------------------------------------------------------------------------
// Kernel 2: 2-combo fp16 screening (exact x . c_hi) + best-2 + fp32 refine
// ---------------------------------------------------------------------------
__global__ __launch_bounds__(THREADS, 1)
void vq_tc(const float* __restrict__ inputs,
           const float* __restrict__ codebook,
           float* __restrict__ out_q,
           float* __restrict__ out_tok) {
    extern __shared__ float smf[];
    const uint32_t smb = smem_u32(smf);
    float* s_cn = (float*)((char*)smf + SMB_CN);
    float* s_rd = (float*)((char*)smf + SMB_RED);

    const int tid  = threadIdx.x;
    const int w    = tid >> 5;
    const int lane = tid & 31;
    const int grp  = lane >> 2;        // m-row within tile (0..7)
    const int qt   = lane & 3;         // k-thread in quad

    const int r0 = blockIdx.x * M_CTA + w * 16 + grp;
    const int r1 = r0 + 8;

    // ---- A fragments: fp16 hi/lo split, registers only ----
    uint32_t ahi[4][4], alo[4][4];
    {
        const float* x0 = inputs + (size_t)r0 * DIM;
        const float* x1 = inputs + (size_t)r1 * DIM;
        #pragma unroll
        for (int s = 0; s < 4; s++) {
            const int k0 = 16 * s + 2 * qt;
            split2(*(const float2*)(x0 + k0),     ahi[s][0], alo[s][0]);
            split2(*(const float2*)(x1 + k0),     ahi[s][1], alo[s][1]);
            split2(*(const float2*)(x0 + k0 + 8), ahi[s][2], alo[s][2]);
            split2(*(const float2*)(x1 + k0 + 8), ahi[s][3], alo[s][3]);
        }
    }

    // ---- cnorm to smem ----
    #pragma unroll
    for (int i = tid; i < KCODES; i += THREADS) s_cn[i] = g_cnorm[i];

    // ---- B chunk loader: hi plane only, 2 x cp.async(16B) per thread ----
    const int lnl = tid >> 2;          // code within chunk (0..127)
    const int lq  = tid & 3;           // quarter -> k-units 2q, 2q+1
    #define LOAD_CHUNK(c, buf) do {                                                  \
        const __half* _src = g_cbh + ((size_t)((c) * CHUNK_N + lnl)) * DIM + lq * 16;\
        uint32_t _dst = smb + SMB_B + (uint32_t)((buf) * 16384 + lnl * 128);         \
        _Pragma("unroll")                                                            \
        for (int _j = 0; _j < 2; _j++) {                                             \
            int _u = lq * 2 + _j;                                                    \
            cp_async16(_dst + ((_u ^ (lnl & 7)) * 16), _src + _j * 8);               \
        }                                                                            \
        CP_COMMIT();                                                                 \
    } while (0)

    LOAD_CHUNK(0, 0);

    // ldmatrix per-lane address components
    const int nloc = ((lane >> 4) & 1) * 8 + (lane & 7);  // B row within pair
    const int ubit = (lane >> 3) & 1;                     // k-unit parity
    const int s7   = lane & 7;                            // swizzle key

    float b1[2] = { 3.402823466e38f, 3.402823466e38f };
    float b2[2] = { 3.402823466e38f, 3.402823466e38f };
    int   i1[2] = { 0, 0 }, i2[2] = { 0, 0 };

    for (int c = 0; c < NCHUNKS; c++) {
        if (c + 1 < NCHUNKS) {
            LOAD_CHUNK(c + 1, (c + 1) & 1);
            asm volatile("cp.async.wait_group 1;" ::: "memory");
        } else {
            asm volatile("cp.async.wait_group 0;" ::: "memory");
        }
        __syncthreads();

        const uint32_t rowH = smb + SMB_B + (uint32_t)((c & 1) * 16384) + nloc * 128;

        #pragma unroll
        for (int p = 0; p < 8; p++) {           // pair of n-frags = 16 codes
            float acc0[4] = {0.f, 0.f, 0.f, 0.f};
            float acc1[4] = {0.f, 0.f, 0.f, 0.f};
            const uint32_t rbase = rowH + p * 2048;

            #pragma unroll
            for (int s = 0; s < 4; s++) {       // k16 steps
                const uint32_t uoff = (uint32_t)(((2 * s + ubit) ^ s7) * 16);
                uint32_t bh0, bh1, bh2, bh3;
                LDM4(bh0, bh1, bh2, bh3, rbase + uoff);    // hi B
                mma_f16(acc0, ahi[s], bh0, bh1);   // hi*hi
                mma_f16(acc1, ahi[s], bh2, bh3);
                mma_f16(acc0, alo[s], bh0, bh1);   // lo*hi
                mma_f16(acc1, alo[s], bh2, bh3);
            }

            // epilogue: dist = |c|^2 - 2*dot, best-2 (ascending index order)
            const int g0 = c * CHUNK_N + p * 16 + 2 * qt;
            const int g1 = g0 + 8;
            const float cn00 = s_cn[g0], cn01 = s_cn[g0 + 1];
            const float cn10 = s_cn[g1], cn11 = s_cn[g1 + 1];
            upd2(b1[0], i1[0], b2[0], i2[0], cn00 - 2.0f * acc0[0], g0);
            upd2(b1[0], i1[0], b2[0], i2[0], cn01 - 2.0f * acc0[1], g0 + 1);
            upd2(b1[1], i1[1], b2[1], i2[1], cn00 - 2.0f * acc0[2], g0);
            upd2(b1[1], i1[1], b2[1], i2[1], cn01 - 2.0f * acc0[3], g0 + 1);
            upd2(b1[0], i1[0], b2[0], i2[0], cn10 - 2.0f * acc1[0], g1);
            upd2(b1[0], i1[0], b2[0], i2[0], cn11 - 2.0f * acc1[1], g1 + 1);
            upd2(b1[1], i1[1], b2[1], i2[1], cn10 - 2.0f * acc1[2], g1);
            upd2(b1[1], i1[1], b2[1], i2[1], cn11 - 2.0f * acc1[3], g1 + 1);
        }
        __syncthreads();
    }

    // ---- per-row best-2 merge across the 4 k-lanes, then UNCONDITIONAL
    //      exact fp32 refine (all lanes execute every shuffle) ----
    float sse = 0.f;
    #pragma unroll
    for (int mt = 0; mt < 2; mt++) {
        float B1 = b1[mt], B2 = b2[mt];
        int   I1 = i1[mt], I2 = i2[mt];
        #pragma unroll
        for (int off = 1; off <= 2; off <<= 1) {
            float c1 = __shfl_xor_sync(0xffffffffu, B1, off);
            int  ci1 = __shfl_xor_sync(0xffffffffu, I1, off);
            float c2 = __shfl_xor_sync(0xffffffffu, B2, off);
            int  ci2 = __shfl_xor_sync(0xffffffffu, I2, off);
            merge2(B1, I1, B2, I2, c1, ci1, c2, ci2);
        }

        const int row = mt ? r1 : r0;

        // exact fp32 distances for both candidates (cooperative over quad)
        const float* xr  = inputs + (size_t)row * DIM + qt * 16;
        const float* c1p = codebook + (size_t)I1 * DIM + qt * 16;
        const float* c2p = codebook + (size_t)I2 * DIM + qt * 16;
        float p1 = 0.f, p2 = 0.f;
        #pragma unroll
        for (int j = 0; j < 16; j++) {
            float xv = xr[j];
            p1 = fmaf(xv, c1p[j], p1);
            p2 = fmaf(xv, c2p[j], p2);
        }
        #pragma unroll
        for (int off = 1; off <= 2; off <<= 1) {
            p1 += __shfl_xor_sync(0xffffffffu, p1, off);
            p2 += __shfl_xor_sync(0xffffffffu, p2, off);
        }
        float e1 = s_cn[I1] - 2.0f * p1;
        float e2 = s_cn[I2] - 2.0f * p2;
        const int sel = dless(e2, I2, e1, I1) ? I2 : I1;

        const float4* cq  = (const float4*)(codebook + (size_t)sel * DIM) + qt * 4;
        const float4* xin = (const float4*)(inputs + (size_t)row * DIM) + qt * 4;
        float4* oq = (float4*)(out_q + (size_t)row * DIM) + qt * 4;
        #pragma unroll
        for (int g = 0; g < 4; g++) {
            float4 q = cq[g], x = xin[g];
            float dx = q.x - x.x, dy = q.y - x.y, dz = q.z - x.z, dw = q.w - x.w;
            sse += dx * dx + dy * dy + dz * dz + dw * dw;
            oq[g] = q;
        }
        if (qt == 0) {
            out_tok[row] = (float)sel;
            atomicAdd(&g_counts[sel], 1u);
        }
    }

    // ---- SSE block reduce ----
    #pragma unroll
    for (int o = 16; o > 0; o >>= 1) sse += __shfl_down_sync(0xffffffffu, sse, o);
    if (lane == 0) s_rd[w] = sse;
    __syncthreads();
    if (tid == 0) {
        float s = 0.f;
        #pragma unroll
        for (int i = 0; i < 16; i++) s += s_rd[i];
        atomicAdd(&g_sse, (double)s);
    }
}

// ---------------------------------------------------------------------------
// Kernel 3: perplexity + scalar losses
// ---------------------------------------------------------------------------
__global__ void vq_finalize(float* __restrict__ out_scalars) {
    __shared__ double s_red[32];
    const int j = threadIdx.x;
    double p    = (double)g_counts[j] / (double)N_ROWS;
    double term = p * log(p + 1e-10);
    #pragma unroll
    for (int o = 16; o > 0; o >>= 1)
        term += __shfl_down_sync(0xffffffffu, term, o);
    const int lane = j & 31, wid = j >> 5;
    if (lane == 0) s_red[wid] = term;
    __syncthreads();
    if (j == 0) {
        double tot = 0.0;
        #pragma unroll
        for (int w = 0; w < 32; w++) tot += s_red[w];
        double perp = exp(-tot);
        double L = g_sse / (double)ND_ELEMS;
        out_scalars[0] = (float)(1.25 * L);
        out_scalars[1] = (float)(0.25 * L);
        out_scalars[2] = (float)L;
        out_scalars[3] = (float)perp;
    }
}

// ---------------------------------------------------------------------------
extern "C" void kernel_launch(void* const* d_in, const int* in_sizes, int n_in,
                              void* d_out, int out_size) {
    const float* inputs   = (const float*)d_in[0];
    const float* codebook = (const float*)d_in[1];
    float* out = (float*)d_out;

    float* out_q       = out;
    float* out_tok     = out + ND_ELEMS;
    float* out_scalars = out + ND_ELEMS + N_ROWS;

    static int configured = 0;
    if (!configured) {
        cudaFuncSetAttribute(vq_tc, cudaFuncAttributeMaxDynamicSharedMemorySize, SMEM_BYTES);
        configured = 1;
    }

    vq_split<<<KCODES * DIM / 1024, 1024>>>(codebook);
    vq_tc<<<CTAS, THREADS, SMEM_BYTES>>>(inputs, codebook, out_q, out_tok);
    vq_finalize<<<1, 1024>>>(out_scalars);
}